// round 4
// baseline (speedup 1.0000x reference)
#include <cuda_runtime.h>
#include <cuda_bf16.h>

// ---------------------------------------------------------------------------
// Compile-time algebra tables for Cl(3,0,1)
// ---------------------------------------------------------------------------
__host__ __device__ constexpr int PC4(int x) {
    return ((x >> 0) & 1) + ((x >> 1) & 1) + ((x >> 2) & 1) + ((x >> 3) & 1);
}

__host__ __device__ constexpr float SGN(int a, int b) {
    int s = 0;
    int aa = a >> 1;
    while (aa) { s += PC4(aa & b); aa >>= 1; }
    return (s & 1) ? -1.0f : 1.0f;
}

struct GPTab { int a[192]; int b[192]; int k[192]; float s[192]; };
__host__ __device__ constexpr GPTab make_gp() {
    GPTab t{};
    int n = 0;
    for (int a = 0; a < 16; a++)
        for (int b = 0; b < 16; b++)
            if (!(a & b & 1)) {
                t.a[n] = a; t.b[n] = b; t.k[n] = a ^ b; t.s[n] = SGN(a, b);
                n++;
            }
    return t;
}

struct JTab { int a[81]; int b[81]; int k[81]; float s[81]; };
__host__ __device__ constexpr JTab make_j() {
    JTab t{};
    int n = 0;
    for (int i = 0; i < 16; i++)
        for (int j = 0; j < 16; j++)
            if ((i | j) == 15) {
                int p = i ^ 15, q = j ^ 15, k = i & j, r = k ^ 15;
                t.a[n] = i; t.b[n] = j; t.k[n] = k;
                t.s[n] = SGN(i, p) * SGN(j, q) * SGN(p, q) * SGN(k, r);
                n++;
            }
    return t;
}

__device__ constexpr GPTab GPT = make_gp();
__device__ constexpr JTab  JT  = make_j();
__device__ constexpr int PCY[16] = {0,1,1,2,1,2,2,3,1,2,2,3,2,3,3,4};

// ---------------------------------------------------------------------------
// Packed f32x2 helpers (sm_100+)
// ---------------------------------------------------------------------------
typedef unsigned long long u64;

#define FMA2(acc, w, v) asm("fma.rn.f32x2 %0, %1, %2, %0;" : "+l"(acc) : "l"(w), "l"(v))
#define MUL2(d, a, b)   asm("mul.rn.f32x2 %0, %1, %2;"     : "=l"(d)  : "l"(a), "l"(b))
#define PACK2(d, f)     asm("mov.b64 %0, {%1, %1};"        : "=l"(d)  : "f"(f))
#define PACK2AB(d, a, b) asm("mov.b64 %0, {%1, %2};"       : "=l"(d)  : "f"(a), "f"(b))
#define UNPACK2(lo, hi, v) asm("mov.b64 {%0, %1}, %2;"     : "=f"(lo), "=f"(hi) : "l"(v))

// ---------------------------------------------------------------------------
// Fused kernel, f32x2-packed over position pairs.
//   grid.y = 4 groups: (branch = gp|join) x (channel half)
//   Block: 2 weight sets for 32 channels in smem, streams 32-position chunks.
//   Threads: 256 = 32 channels x 8 position slots; 4 positions per thread,
//   processed as 2 packed pairs.
// ---------------------------------------------------------------------------
#define THREADS 256
#define WS_FLOATS (2 * 9 * 64 * 32)   // 36864
#define IQ_STRIDE 580                  // 16*36=576 used, +4 pad (bank spread)
#define XS_FLOATS (8 * IQ_STRIDE)      // 4640

__global__ __launch_bounds__(THREADS, 1)
void gbl_kernel(const float* __restrict__ x, const float* __restrict__ ref,
                const float* __restrict__ wg1, const float* __restrict__ wg2,
                const float* __restrict__ wj1, const float* __restrict__ wj2,
                float* __restrict__ out, int nPos)
{
    extern __shared__ float sm[];
    float* ws = sm;                 // [2][9][64][32]
    float* xs = sm + WS_FLOATS;     // [8 iq][16 y][36 pos-swizzled]

    const int tid   = threadIdx.x;
    const int c     = tid & 31;
    const int pslot = tid >> 5;
    const int group  = blockIdx.y;
    const int branch = group >> 1;   // 0 = gp, 1 = join
    const int chalf  = group & 1;

    const float* wA = branch ? wj1 : wg1;
    const float* wB = branch ? wj2 : wg2;

    // --- Weight slices to smem ---
    {
        const float* srcA = wA + chalf * 32 * 576;   // w[j][i][b]
        const float* srcB = wB + chalf * 32 * 576;
        for (int e = tid; e < 18432; e += THREADS) {
            int cc  = e / 576;
            int rem = e - cc * 576;
            int ii  = rem / 9;
            int bb  = rem - ii * 9;
            ws[(bb * 64 + ii) * 32 + cc]        = srcA[e];
            ws[((9 + bb) * 64 + ii) * 32 + cc]  = srcB[e];
        }
    }
    __syncthreads();

    u64 pone2, mone2, sc2;
    PACK2(pone2, 1.0f);
    PACK2(mone2, -1.0f);
    PACK2(sc2, 1e-5f);

    const int cout = branch * 64 + chalf * 32 + c;
    const int nChunk = nPos >> 5;
    const float4* xb4 = (const float4*)x;

    for (int chunk = blockIdx.x; chunk < nChunk; chunk += gridDim.x) {
        const int p0 = chunk << 5;

        u64 aA[2][16], aB[2][16];
        #pragma unroll
        for (int pr = 0; pr < 2; pr++)
            #pragma unroll
            for (int y = 0; y < 16; y++) { aA[pr][y] = 0ull; aB[pr][y] = 0ull; }

        // Prefetch i-chunk 0
        float4 pf[4];
        #pragma unroll
        for (int k = 0; k < 4; k++) {
            int f = tid + k * THREADS;
            int q = f & 3, iq = (f >> 2) & 7, pp = f >> 5;
            pf[k] = xb4[((size_t)(p0 + pp) * 64 + iq) * 4 + q];
        }

        for (int ic = 0; ic < 64; ic += 8) {
            __syncthreads();
            #pragma unroll
            for (int k = 0; k < 4; k++) {
                int f = tid + k * THREADS;
                int q = f & 3, iq = (f >> 2) & 7, pp = f >> 5;
                float vals[4] = {pf[k].x, pf[k].y, pf[k].z, pf[k].w};
                #pragma unroll
                for (int t = 0; t < 4; t++) {
                    int yy = q * 4 + t;
                    xs[iq * IQ_STRIDE + yy * 36 + (pp & 3) + ((((pp >> 2) ^ yy) & 7) << 2)] = vals[t];
                }
            }
            __syncthreads();

            if (ic < 56) {
                #pragma unroll
                for (int k = 0; k < 4; k++) {
                    int f = tid + k * THREADS;
                    int q = f & 3, iq = (f >> 2) & 7, pp = f >> 5;
                    pf[k] = xb4[((size_t)(p0 + pp) * 64 + (ic + 8 + iq)) * 4 + q];
                }
            }

            #pragma unroll 2
            for (int iq = 0; iq < 8; iq++) {
                const int i = ic + iq;
                u64 wa2[9], wb2[9];
                #pragma unroll
                for (int b = 0; b < 9; b++) {
                    float wa = ws[(b * 64 + i) * 32 + c];
                    float wb = ws[((9 + b) * 64 + i) * 32 + c];
                    PACK2(wa2[b], wa);
                    PACK2(wb2[b], wb);
                }
                const float* xp = xs + iq * IQ_STRIDE;
                #pragma unroll
                for (int t = 0; t < 8; t++) {
                    const int ye = 2 * t, yo = 2 * t + 1;
                    const int pe = PCY[ye], po = PCY[yo];
                    ulonglong2 ve = *(const ulonglong2*)(xp + ye * 36 + ((pslot ^ (ye & 7)) << 2));
                    ulonglong2 vo = *(const ulonglong2*)(xp + yo * 36 + ((pslot ^ (yo & 7)) << 2));
                    // even comp: diagonal term only
                    FMA2(aA[0][ye], wa2[pe], ve.x); FMA2(aA[1][ye], wa2[pe], ve.y);
                    FMA2(aB[0][ye], wb2[pe], ve.x); FMA2(aB[1][ye], wb2[pe], ve.y);
                    // odd comp: diagonal + e0-shift term (source = even partner)
                    FMA2(aA[0][yo], wa2[po], vo.x); FMA2(aA[1][yo], wa2[po], vo.y);
                    FMA2(aB[0][yo], wb2[po], vo.x); FMA2(aB[1][yo], wb2[po], vo.y);
                    FMA2(aA[0][yo], wa2[4 + po], ve.x); FMA2(aA[1][yo], wa2[4 + po], ve.y);
                    FMA2(aB[0][yo], wb2[4 + po], ve.x); FMA2(aB[1][yo], wb2[4 + po], ve.y);
                }
            }
        }

        // --- Bilinear (packed over position pairs) + store ---
        #pragma unroll
        for (int pr = 0; pr < 2; pr++) {
            u64 o2[16];
            #pragma unroll
            for (int y = 0; y < 16; y++) o2[y] = 0ull;

            if (branch == 0) {
                #pragma unroll
                for (int e = 0; e < 192; e++) {
                    u64 m;
                    MUL2(m, aA[pr][GPT.a[e]], aB[pr][GPT.b[e]]);
                    const u64 s2 = (GPT.s[e] > 0.0f) ? pone2 : mone2;
                    FMA2(o2[GPT.k[e]], m, s2);
                }
                #pragma unroll
                for (int y = 0; y < 16; y++) MUL2(o2[y], o2[y], sc2);
            } else {
                #pragma unroll
                for (int e = 0; e < 81; e++) {
                    u64 m;
                    MUL2(m, aA[pr][JT.a[e]], aB[pr][JT.b[e]]);
                    const u64 s2 = (JT.s[e] > 0.0f) ? pone2 : mone2;
                    FMA2(o2[JT.k[e]], m, s2);
                }
                const int pbase = p0 + pslot * 4 + pr * 2;
                float r0 = __ldg(ref + (size_t)pbase * 16 + 15);
                float r1 = __ldg(ref + (size_t)(pbase + 1) * 16 + 15);
                u64 r2;
                PACK2AB(r2, r0, r1);
                #pragma unroll
                for (int y = 0; y < 16; y++) MUL2(o2[y], o2[y], r2);
            }

            // unpack and store two positions
            float olo[16], ohi[16];
            #pragma unroll
            for (int y = 0; y < 16; y++) UNPACK2(olo[y], ohi[y], o2[y]);

            const int pbase = p0 + pslot * 4 + pr * 2;
            float4* op0 = (float4*)(out + ((size_t)pbase * 128 + cout) * 16);
            float4* op1 = (float4*)(out + ((size_t)(pbase + 1) * 128 + cout) * 16);
            op0[0] = make_float4(olo[0],  olo[1],  olo[2],  olo[3]);
            op0[1] = make_float4(olo[4],  olo[5],  olo[6],  olo[7]);
            op0[2] = make_float4(olo[8],  olo[9],  olo[10], olo[11]);
            op0[3] = make_float4(olo[12], olo[13], olo[14], olo[15]);
            op1[0] = make_float4(ohi[0],  ohi[1],  ohi[2],  ohi[3]);
            op1[1] = make_float4(ohi[4],  ohi[5],  ohi[6],  ohi[7]);
            op1[2] = make_float4(ohi[8],  ohi[9],  ohi[10], ohi[11]);
            op1[3] = make_float4(ohi[12], ohi[13], ohi[14], ohi[15]);
        }
    }
}

// ---------------------------------------------------------------------------
extern "C" void kernel_launch(void* const* d_in, const int* in_sizes, int n_in,
                              void* d_out, int out_size) {
    const float* x   = (const float*)d_in[0];
    const float* ref = (const float*)d_in[1];
    const float* wg1 = (const float*)d_in[2];
    const float* wg2 = (const float*)d_in[3];
    const float* wj1 = (const float*)d_in[4];
    const float* wj2 = (const float*)d_in[5];
    float* out = (float*)d_out;

    const int nPos = in_sizes[0] / (64 * 16);   // 16384

    const int smem = (WS_FLOATS + XS_FLOATS) * sizeof(float);   // ~166 KB
    cudaFuncSetAttribute(gbl_kernel, cudaFuncAttributeMaxDynamicSharedMemorySize, smem);

    dim3 grid(37, 4);   // 148 blocks = 1 wave at 1 block/SM
    gbl_kernel<<<grid, THREADS, smem>>>(x, ref, wg1, wg2, wj1, wj2, out, nPos);
}

// round 5
// speedup vs baseline: 1.0001x; 1.0001x over previous
#include <cuda_runtime.h>
#include <cuda_bf16.h>

// ---------------------------------------------------------------------------
// Compile-time algebra tables for Cl(3,0,1)
// ---------------------------------------------------------------------------
__host__ __device__ constexpr int PC4(int x) {
    return ((x >> 0) & 1) + ((x >> 1) & 1) + ((x >> 2) & 1) + ((x >> 3) & 1);
}

__host__ __device__ constexpr float SGN(int a, int b) {
    int s = 0;
    int aa = a >> 1;
    while (aa) { s += PC4(aa & b); aa >>= 1; }
    return (s & 1) ? -1.0f : 1.0f;
}

struct GPTab { int a[192]; int b[192]; int k[192]; float s[192]; };
__host__ __device__ constexpr GPTab make_gp() {
    GPTab t{};
    int n = 0;
    for (int a = 0; a < 16; a++)
        for (int b = 0; b < 16; b++)
            if (!(a & b & 1)) {
                t.a[n] = a; t.b[n] = b; t.k[n] = a ^ b; t.s[n] = SGN(a, b);
                n++;
            }
    return t;
}

struct JTab { int a[81]; int b[81]; int k[81]; float s[81]; };
__host__ __device__ constexpr JTab make_j() {
    JTab t{};
    int n = 0;
    for (int i = 0; i < 16; i++)
        for (int j = 0; j < 16; j++)
            if ((i | j) == 15) {
                int p = i ^ 15, q = j ^ 15, k = i & j, r = k ^ 15;
                t.a[n] = i; t.b[n] = j; t.k[n] = k;
                t.s[n] = SGN(i, p) * SGN(j, q) * SGN(p, q) * SGN(k, r);
                n++;
            }
    return t;
}

__device__ constexpr GPTab GPT = make_gp();
__device__ constexpr JTab  JT  = make_j();
__device__ constexpr int PCY[16] = {0,1,1,2,1,2,2,3,1,2,2,3,2,3,3,4};

// ---------------------------------------------------------------------------
// Packed f32x2 helpers (sm_100+)
// ---------------------------------------------------------------------------
typedef unsigned long long u64;

#define FMA2(acc, w, v) asm("fma.rn.f32x2 %0, %1, %2, %0;" : "+l"(acc) : "l"(w), "l"(v))
#define MUL2(d, a, b)   asm("mul.rn.f32x2 %0, %1, %2;"     : "=l"(d)  : "l"(a), "l"(b))
#define PACK2(d, f)     asm("mov.b64 %0, {%1, %1};"        : "=l"(d)  : "f"(f))
#define PACK2AB(d, a, b) asm("mov.b64 %0, {%1, %2};"       : "=l"(d)  : "f"(a), "f"(b))
#define UNPACK2(lo, hi, v) asm("mov.b64 {%0, %1}, %2;"     : "=f"(lo), "=f"(hi) : "l"(v))

// ---------------------------------------------------------------------------
// Fused kernel, f32x2-packed over position pairs.
//   grid.y = 4 groups: (branch = gp|join) x (channel half)
//   Block: 2 weight sets for 32 channels in smem, streams 32-position chunks.
//   Threads: 256 = 32 channels x 8 position slots; 4 positions per thread,
//   processed as 2 packed pairs.
// ---------------------------------------------------------------------------
#define THREADS 256
#define WS_FLOATS (2 * 9 * 64 * 32)   // 36864
#define IQ_STRIDE 580                  // 16*36=576 used, +4 pad (bank spread)
#define XS_FLOATS (8 * IQ_STRIDE)      // 4640

__global__ __launch_bounds__(THREADS, 1)
void gbl_kernel(const float* __restrict__ x, const float* __restrict__ ref,
                const float* __restrict__ wg1, const float* __restrict__ wg2,
                const float* __restrict__ wj1, const float* __restrict__ wj2,
                float* __restrict__ out, int nPos)
{
    extern __shared__ float sm[];
    float* ws = sm;                 // [2][9][64][32]
    float* xs = sm + WS_FLOATS;     // [8 iq][16 y][36 pos-swizzled]

    const int tid   = threadIdx.x;
    const int c     = tid & 31;
    const int pslot = tid >> 5;
    const int group  = blockIdx.y;
    const int branch = group >> 1;   // 0 = gp, 1 = join
    const int chalf  = group & 1;

    const float* wA = branch ? wj1 : wg1;
    const float* wB = branch ? wj2 : wg2;

    // --- Weight slices to smem ---
    {
        const float* srcA = wA + chalf * 32 * 576;   // w[j][i][b]
        const float* srcB = wB + chalf * 32 * 576;
        for (int e = tid; e < 18432; e += THREADS) {
            int cc  = e / 576;
            int rem = e - cc * 576;
            int ii  = rem / 9;
            int bb  = rem - ii * 9;
            ws[(bb * 64 + ii) * 32 + cc]        = srcA[e];
            ws[((9 + bb) * 64 + ii) * 32 + cc]  = srcB[e];
        }
    }
    __syncthreads();

    u64 pone2, mone2, sc2;
    PACK2(pone2, 1.0f);
    PACK2(mone2, -1.0f);
    PACK2(sc2, 1e-5f);

    const int cout = branch * 64 + chalf * 32 + c;
    const int nChunk = nPos >> 5;
    const float4* xb4 = (const float4*)x;

    for (int chunk = blockIdx.x; chunk < nChunk; chunk += gridDim.x) {
        const int p0 = chunk << 5;

        u64 aA[2][16], aB[2][16];
        #pragma unroll
        for (int pr = 0; pr < 2; pr++)
            #pragma unroll
            for (int y = 0; y < 16; y++) { aA[pr][y] = 0ull; aB[pr][y] = 0ull; }

        // Prefetch i-chunk 0
        float4 pf[4];
        #pragma unroll
        for (int k = 0; k < 4; k++) {
            int f = tid + k * THREADS;
            int q = f & 3, iq = (f >> 2) & 7, pp = f >> 5;
            pf[k] = xb4[((size_t)(p0 + pp) * 64 + iq) * 4 + q];
        }

        for (int ic = 0; ic < 64; ic += 8) {
            __syncthreads();
            #pragma unroll
            for (int k = 0; k < 4; k++) {
                int f = tid + k * THREADS;
                int q = f & 3, iq = (f >> 2) & 7, pp = f >> 5;
                float vals[4] = {pf[k].x, pf[k].y, pf[k].z, pf[k].w};
                #pragma unroll
                for (int t = 0; t < 4; t++) {
                    int yy = q * 4 + t;
                    xs[iq * IQ_STRIDE + yy * 36 + (pp & 3) + ((((pp >> 2) ^ yy) & 7) << 2)] = vals[t];
                }
            }
            __syncthreads();

            if (ic < 56) {
                #pragma unroll
                for (int k = 0; k < 4; k++) {
                    int f = tid + k * THREADS;
                    int q = f & 3, iq = (f >> 2) & 7, pp = f >> 5;
                    pf[k] = xb4[((size_t)(p0 + pp) * 64 + (ic + 8 + iq)) * 4 + q];
                }
            }

            #pragma unroll 2
            for (int iq = 0; iq < 8; iq++) {
                const int i = ic + iq;
                u64 wa2[9], wb2[9];
                #pragma unroll
                for (int b = 0; b < 9; b++) {
                    float wa = ws[(b * 64 + i) * 32 + c];
                    float wb = ws[((9 + b) * 64 + i) * 32 + c];
                    PACK2(wa2[b], wa);
                    PACK2(wb2[b], wb);
                }
                const float* xp = xs + iq * IQ_STRIDE;
                #pragma unroll
                for (int t = 0; t < 8; t++) {
                    const int ye = 2 * t, yo = 2 * t + 1;
                    const int pe = PCY[ye], po = PCY[yo];
                    ulonglong2 ve = *(const ulonglong2*)(xp + ye * 36 + ((pslot ^ (ye & 7)) << 2));
                    ulonglong2 vo = *(const ulonglong2*)(xp + yo * 36 + ((pslot ^ (yo & 7)) << 2));
                    // even comp: diagonal term only
                    FMA2(aA[0][ye], wa2[pe], ve.x); FMA2(aA[1][ye], wa2[pe], ve.y);
                    FMA2(aB[0][ye], wb2[pe], ve.x); FMA2(aB[1][ye], wb2[pe], ve.y);
                    // odd comp: diagonal + e0-shift term (source = even partner)
                    FMA2(aA[0][yo], wa2[po], vo.x); FMA2(aA[1][yo], wa2[po], vo.y);
                    FMA2(aB[0][yo], wb2[po], vo.x); FMA2(aB[1][yo], wb2[po], vo.y);
                    FMA2(aA[0][yo], wa2[4 + po], ve.x); FMA2(aA[1][yo], wa2[4 + po], ve.y);
                    FMA2(aB[0][yo], wb2[4 + po], ve.x); FMA2(aB[1][yo], wb2[4 + po], ve.y);
                }
            }
        }

        // --- Bilinear (packed over position pairs) + store ---
        #pragma unroll
        for (int pr = 0; pr < 2; pr++) {
            u64 o2[16];
            #pragma unroll
            for (int y = 0; y < 16; y++) o2[y] = 0ull;

            if (branch == 0) {
                #pragma unroll
                for (int e = 0; e < 192; e++) {
                    u64 m;
                    MUL2(m, aA[pr][GPT.a[e]], aB[pr][GPT.b[e]]);
                    const u64 s2 = (GPT.s[e] > 0.0f) ? pone2 : mone2;
                    FMA2(o2[GPT.k[e]], m, s2);
                }
                #pragma unroll
                for (int y = 0; y < 16; y++) MUL2(o2[y], o2[y], sc2);
            } else {
                #pragma unroll
                for (int e = 0; e < 81; e++) {
                    u64 m;
                    MUL2(m, aA[pr][JT.a[e]], aB[pr][JT.b[e]]);
                    const u64 s2 = (JT.s[e] > 0.0f) ? pone2 : mone2;
                    FMA2(o2[JT.k[e]], m, s2);
                }
                const int pbase = p0 + pslot * 4 + pr * 2;
                float r0 = __ldg(ref + (size_t)pbase * 16 + 15);
                float r1 = __ldg(ref + (size_t)(pbase + 1) * 16 + 15);
                u64 r2;
                PACK2AB(r2, r0, r1);
                #pragma unroll
                for (int y = 0; y < 16; y++) MUL2(o2[y], o2[y], r2);
            }

            // unpack and store two positions
            float olo[16], ohi[16];
            #pragma unroll
            for (int y = 0; y < 16; y++) UNPACK2(olo[y], ohi[y], o2[y]);

            const int pbase = p0 + pslot * 4 + pr * 2;
            float4* op0 = (float4*)(out + ((size_t)pbase * 128 + cout) * 16);
            float4* op1 = (float4*)(out + ((size_t)(pbase + 1) * 128 + cout) * 16);
            op0[0] = make_float4(olo[0],  olo[1],  olo[2],  olo[3]);
            op0[1] = make_float4(olo[4],  olo[5],  olo[6],  olo[7]);
            op0[2] = make_float4(olo[8],  olo[9],  olo[10], olo[11]);
            op0[3] = make_float4(olo[12], olo[13], olo[14], olo[15]);
            op1[0] = make_float4(ohi[0],  ohi[1],  ohi[2],  ohi[3]);
            op1[1] = make_float4(ohi[4],  ohi[5],  ohi[6],  ohi[7]);
            op1[2] = make_float4(ohi[8],  ohi[9],  ohi[10], ohi[11]);
            op1[3] = make_float4(ohi[12], ohi[13], ohi[14], ohi[15]);
        }
    }
}

// ---------------------------------------------------------------------------
extern "C" void kernel_launch(void* const* d_in, const int* in_sizes, int n_in,
                              void* d_out, int out_size) {
    const float* x   = (const float*)d_in[0];
    const float* ref = (const float*)d_in[1];
    const float* wg1 = (const float*)d_in[2];
    const float* wg2 = (const float*)d_in[3];
    const float* wj1 = (const float*)d_in[4];
    const float* wj2 = (const float*)d_in[5];
    float* out = (float*)d_out;

    const int nPos = in_sizes[0] / (64 * 16);   // 16384

    const int smem = (WS_FLOATS + XS_FLOATS) * sizeof(float);   // ~166 KB
    cudaFuncSetAttribute(gbl_kernel, cudaFuncAttributeMaxDynamicSharedMemorySize, smem);

    dim3 grid(37, 4);   // 148 blocks = 1 wave at 1 block/SM
    gbl_kernel<<<grid, THREADS, smem>>>(x, ref, wg1, wg2, wj1, wj2, out, nPos);
}

// round 6
// speedup vs baseline: 1.7571x; 1.7570x over previous
#include <cuda_runtime.h>
#include <cuda_bf16.h>
#include <cstdint>

__host__ __device__ constexpr int PC4(int x) {
    return ((x >> 0) & 1) + ((x >> 1) & 1) + ((x >> 2) & 1) + ((x >> 3) & 1);
}
__host__ __device__ constexpr float SGN(int a, int b) {
    int s = 0; int aa = a >> 1;
    while (aa) { s += PC4(aa & b); aa >>= 1; }
    return (s & 1) ? -1.0f : 1.0f;
}
struct GPTab { int a[192]; int b[192]; int k[192]; float s[192]; };
__host__ __device__ constexpr GPTab make_gp() {
    GPTab t{}; int n = 0;
    for (int a = 0; a < 16; a++)
        for (int b = 0; b < 16; b++)
            if (!(a & b & 1)) { t.a[n]=a; t.b[n]=b; t.k[n]=a^b; t.s[n]=SGN(a,b); n++; }
    return t;
}
struct JTab { int a[81]; int b[81]; int k[81]; float s[81]; };
__host__ __device__ constexpr JTab make_j() {
    JTab t{}; int n = 0;
    for (int i = 0; i < 16; i++)
        for (int j = 0; j < 16; j++)
            if ((i | j) == 15) {
                int p = i^15, q = j^15, k = i&j, r = k^15;
                t.a[n]=i; t.b[n]=j; t.k[n]=k;
                t.s[n]=SGN(i,p)*SGN(j,q)*SGN(p,q)*SGN(k,r); n++;
            }
    return t;
}
__device__ constexpr GPTab GPT = make_gp();
__device__ constexpr JTab  JT  = make_j();
__device__ constexpr int PCY[16] = {0,1,1,2,1,2,2,3,1,2,2,3,2,3,3,4};

// D[16p x 8j] += A[16p x 16i](row) * B[16i x 8j](col)
#define MMA(d, a, b) \
    asm("mma.sync.aligned.m16n8k16.row.col.f32.bf16.bf16.f32 " \
        "{%0,%1,%2,%3}, {%4,%5,%6,%7}, {%8,%9}, {%0,%1,%2,%3};" \
        : "+f"(d[0]), "+f"(d[1]), "+f"(d[2]), "+f"(d[3]) \
        : "r"(a[0]), "r"(a[1]), "r"(a[2]), "r"(a[3]), "r"(b[0]), "r"(b[1]))

#define THREADS 256
#define JSTR 144                 // w row: 64 i * 2B + 16B pad
#define WPL  (32 * JSTR)         // 4608 per (ws,b,hl)
#define WSM_BYTES (36 * WPL)     // 165888
#define PSTR 48                  // x row: 16 i * 2B + 16B pad
#define YPL  (32 * PSTR + 8)     // 1544
#define XHL  (16 * YPL)          // 24704
#define XSM_BYTES (2 * XHL)      // 49408
#define SMEM_BYTES (WSM_BYTES + XSM_BYTES)   // 215296

__device__ __forceinline__ uint32_t lds32(const char* p) { return *(const uint32_t*)p; }

__global__ __launch_bounds__(THREADS, 1)
void gbl_kernel(const float* __restrict__ x, const float* __restrict__ ref,
                const float* __restrict__ wg1, const float* __restrict__ wg2,
                const float* __restrict__ wj1, const float* __restrict__ wj2,
                float* __restrict__ out, int nPos)
{
    extern __shared__ char sm[];
    char* wsm = sm;              // [(ws*9+b)*2+hl][j 32][i 64] bf16
    char* xsm = sm + WSM_BYTES;  // [hl][y 16][p 32][i 16] bf16 (per k-block)

    const int tid  = threadIdx.x;
    const int wid  = tid >> 5;
    const int lane = tid & 31;
    const int pt = wid >> 2;     // position tile (16)
    const int jt = wid & 3;      // channel tile (8)
    const int r  = lane >> 2;
    const int q  = lane & 3;

    const int group  = blockIdx.y;
    const int branch = group >> 1;
    const int chalf  = group & 1;
    const float* wA = branch ? wj1 : wg1;
    const float* wB = branch ? wj2 : wg2;

    // ---- stage weights (fp32 -> bf16 hi/lo) ----
    for (int e = tid; e < 36864; e += THREADS) {
        int ws = e / 18432;
        int rem = e - ws * 18432;
        int j = rem / 576;
        int rem2 = rem - j * 576;
        int i = rem2 / 9;
        int b = rem2 - i * 9;
        const float* src = ws ? wB : wA;
        float v = src[(chalf * 32 + j) * 576 + i * 9 + b];
        __nv_bfloat16 h = __float2bfloat16(v);
        __nv_bfloat16 l = __float2bfloat16(v - __bfloat162float(h));
        char* rp = wsm + ((ws * 9 + b) * 2) * WPL + j * JSTR + i * 2;
        *(__nv_bfloat16*)rp = h;
        *(__nv_bfloat16*)(rp + WPL) = l;
    }
    __syncthreads();

    const int cout = branch * 64 + chalf * 32 + jt * 8 + 2 * q;
    const int nChunk = nPos >> 5;
    const float4* xg4 = (const float4*)x;

    const char* wbase = wsm + (jt * 8 + r) * JSTR + q * 4;
    const char* xbase = xsm + (pt * 16 + r) * PSTR + q * 4;

    for (int chunk = blockIdx.x; chunk < nChunk; chunk += gridDim.x) {
        const int p0 = chunk << 5;

        float D[2][16][4];
        #pragma unroll
        for (int ws = 0; ws < 2; ws++)
            #pragma unroll
            for (int y = 0; y < 16; y++)
                #pragma unroll
                for (int k = 0; k < 4; k++) D[ws][y][k] = 0.0f;

        for (int ib = 0; ib < 4; ib++) {
            __syncthreads();
            // ---- stage x k-block: [p 32][i 16][y 16] fp32 -> [hl][y][p][i] bf16
            #pragma unroll
            for (int k = 0; k < 4; k++) {
                int f = tid + k * THREADS;
                int q4 = f & 3, ip = (f >> 2) & 7, p = f >> 5;
                const float4* g = xg4 + ((size_t)(p0 + p) * 64 + ib * 16 + 2 * ip) * 4 + q4;
                float4 v0 = g[0];
                float4 v1 = g[4];
                float e0[4] = {v0.x, v0.y, v0.z, v0.w};
                float e1[4] = {v1.x, v1.y, v1.z, v1.w};
                #pragma unroll
                for (int c = 0; c < 4; c++) {
                    int y = q4 * 4 + c;
                    __nv_bfloat16 h0 = __float2bfloat16(e0[c]);
                    __nv_bfloat16 h1 = __float2bfloat16(e1[c]);
                    __nv_bfloat16 l0 = __float2bfloat16(e0[c] - __bfloat162float(h0));
                    __nv_bfloat16 l1 = __float2bfloat16(e1[c] - __bfloat162float(h1));
                    uint32_t hw = (uint32_t)__bfloat16_as_ushort(h0) |
                                  ((uint32_t)__bfloat16_as_ushort(h1) << 16);
                    uint32_t lw = (uint32_t)__bfloat16_as_ushort(l0) |
                                  ((uint32_t)__bfloat16_as_ushort(l1) << 16);
                    char* d0 = xsm + y * YPL + p * PSTR + ip * 4;
                    *(uint32_t*)d0 = hw;
                    *(uint32_t*)(d0 + XHL) = lw;
                }
            }
            __syncthreads();

            // ---- resident w fragments for this k-block (both wsets) ----
            uint32_t Bw[2][9][2][2];
            #pragma unroll
            for (int ws = 0; ws < 2; ws++)
                #pragma unroll
                for (int b = 0; b < 9; b++)
                    #pragma unroll
                    for (int hl = 0; hl < 2; hl++) {
                        const char* bp = wbase + ((ws * 9 + b) * 2 + hl) * WPL + ib * 32;
                        Bw[ws][b][hl][0] = lds32(bp);
                        Bw[ws][b][hl][1] = lds32(bp + 16);
                    }

            #pragma unroll
            for (int t = 0; t < 8; t++) {
                const int ye = 2 * t, yo = 2 * t + 1;
                const int pe = PCY[ye], po = PCY[yo], bs = 4 + po;
                uint32_t Ax[2][2][4];   // [even/odd y][hi/lo][4]
                #pragma unroll
                for (int yy = 0; yy < 2; yy++)
                    #pragma unroll
                    for (int hl = 0; hl < 2; hl++) {
                        const char* ap = xbase + hl * XHL + (ye + yy) * YPL;
                        Ax[yy][hl][0] = lds32(ap);
                        Ax[yy][hl][1] = lds32(ap + 8 * PSTR);
                        Ax[yy][hl][2] = lds32(ap + 16);
                        Ax[yy][hl][3] = lds32(ap + 8 * PSTR + 16);
                    }
                #pragma unroll
                for (int ws = 0; ws < 2; ws++) {
                    float* De = D[ws][ye];
                    float* Do = D[ws][yo];
                    MMA(De, Ax[0][0], Bw[ws][pe][0]);
                    MMA(De, Ax[0][0], Bw[ws][pe][1]);
                    MMA(De, Ax[0][1], Bw[ws][pe][0]);
                    MMA(Do, Ax[1][0], Bw[ws][po][0]);
                    MMA(Do, Ax[1][0], Bw[ws][po][1]);
                    MMA(Do, Ax[1][1], Bw[ws][po][0]);
                    MMA(Do, Ax[0][0], Bw[ws][bs][0]);   // e0-shift: x[ye] -> E[yo]
                    MMA(Do, Ax[0][0], Bw[ws][bs][1]);
                    MMA(Do, Ax[0][1], Bw[ws][bs][0]);
                }
            }
        }

        // ---- bilinear epilogue + store (exact fp32) ----
        #pragma unroll
        for (int e = 0; e < 4; e++) {
            const int p = p0 + pt * 16 + r + ((e >> 1) * 8);
            const int co = cout + (e & 1);
            float o[16];
            #pragma unroll
            for (int y = 0; y < 16; y++) o[y] = 0.0f;

            if (branch == 0) {
                #pragma unroll
                for (int n = 0; n < 192; n++)
                    o[GPT.k[n]] += GPT.s[n] * D[0][GPT.a[n]][e] * D[1][GPT.b[n]][e];
                #pragma unroll
                for (int y = 0; y < 16; y++) o[y] *= 1e-5f;
            } else {
                #pragma unroll
                for (int n = 0; n < 81; n++)
                    o[JT.k[n]] += JT.s[n] * D[0][JT.a[n]][e] * D[1][JT.b[n]][e];
                const float rr = __ldg(ref + (size_t)p * 16 + 15);
                #pragma unroll
                for (int y = 0; y < 16; y++) o[y] *= rr;
            }

            float4* op = (float4*)(out + ((size_t)p * 128 + co) * 16);
            op[0] = make_float4(o[0],  o[1],  o[2],  o[3]);
            op[1] = make_float4(o[4],  o[5],  o[6],  o[7]);
            op[2] = make_float4(o[8],  o[9],  o[10], o[11]);
            op[3] = make_float4(o[12], o[13], o[14], o[15]);
        }
    }
}

extern "C" void kernel_launch(void* const* d_in, const int* in_sizes, int n_in,
                              void* d_out, int out_size) {
    const float* x   = (const float*)d_in[0];
    const float* ref = (const float*)d_in[1];
    const float* wg1 = (const float*)d_in[2];
    const float* wg2 = (const float*)d_in[3];
    const float* wj1 = (const float*)d_in[4];
    const float* wj2 = (const float*)d_in[5];
    float* out = (float*)d_out;

    const int nPos = in_sizes[0] / (64 * 16);   // 16384

    cudaFuncSetAttribute(gbl_kernel, cudaFuncAttributeMaxDynamicSharedMemorySize, SMEM_BYTES);
    dim3 grid(37, 4);
    gbl_kernel<<<grid, THREADS, SMEM_BYTES>>>(x, ref, wg1, wg2, wj1, wj2, out, nPos);
}